// round 16
// baseline (speedup 1.0000x reference)
#include <cuda_runtime.h>
#include <cuda_bf16.h>
#include <cstdint>
#include <cstddef>

typedef unsigned long long u64;
typedef unsigned int u32;

// ---------------- device scratch (no cudaMalloc allowed) ----------------
// NHWC feature buffers [b][y][x][c], 4*256*256*64 floats each
__device__ float g_h [16777216];
__device__ float g_t1[16777216];
__device__ float g_t2[16777216];
__device__ __align__(16) float g_mean[256];
__device__ __align__(16) float g_rstd[256];
__device__ __align__(16) float g_sum[256];     // zero-init; finalize re-zeroes
__device__ __align__(16) float g_sumsq[256];

// ---------------- helpers ----------------
__device__ __forceinline__ u32 smem_u32(const void* p) {
    u32 a;
    asm("{ .reg .u64 t; cvta.to.shared.u64 t, %1; cvt.u32.u64 %0, t; }"
        : "=r"(a) : "l"(p));
    return a;
}
__device__ __forceinline__ u32 swz(u32 off) { return off ^ ((off >> 3) & 0x70); }
__device__ __forceinline__ int reflx(int i) { return i < 0 ? 1 : (i >= 256 ? 254 : i); }

__device__ __forceinline__ void ldsm4(u32* r, u32 addr) {
    asm volatile("ldmatrix.sync.aligned.m8n8.x4.shared.b16 {%0,%1,%2,%3}, [%4];"
        : "=r"(r[0]), "=r"(r[1]), "=r"(r[2]), "=r"(r[3]) : "r"(addr));
}
__device__ __forceinline__ void mma16816(float* d, const u32* a, const u32* b) {
    asm volatile(
        "mma.sync.aligned.m16n8k16.row.col.f32.bf16.bf16.f32 "
        "{%0,%1,%2,%3}, {%4,%5,%6,%7}, {%8,%9}, {%0,%1,%2,%3};"
        : "+f"(d[0]), "+f"(d[1]), "+f"(d[2]), "+f"(d[3])
        : "r"(a[0]), "r"(a[1]), "r"(a[2]), "r"(a[3]), "r"(b[0]), "r"(b[1]));
}
#define GBAR(id) asm volatile("bar.sync %0, 64;" :: "r"(id) : "memory")

// ---------------- smem layout (relative to 1024-aligned base) ----------------
// [0     : 256   ) bias (64 f32)
// [512   : 9728  ) s_k  float [8 groups][9][32]: slot0 = k_8, slots1-8 = ratios
// [10240 : 157696) W tiles: [tap][hi/lo][64 oc][128B row], swizzled (9*16384)
// [157696: 227328) A tiles: 8 groups x 8704 B (34 rows x 128B, hi then lo)
//                  (FINAL epilogue overlays the group's A region: [32][66] f32)
#define BIAS_OFF  0
#define K_OFF     512
#define W_OFF     10240
#define A_OFF     157696
#define A_STRIDE  8704
#define A_LO_REL  4352
#define DSMEM     (227328 + 1024)

// =======================================================================
// PAC conv via mma.sync, shifted-ldmatrix implicit GEMM.
// bf16 hi/lo split (3 passes), fp32 accum; guide kernel applied via fp32
// accumulator ratio-rescaling. Ratios computed as independent parallel
// exps: ratio_t = exp(0.5*(d_t^2 - d_{t-1}^2)) = k_{t-1}/k_t (no serial
// chain, no division; arg clamped at 65).
// A-build LDGs prefetched to registers; prefetch issued BEFORE the build
// barrier so global latency overlaps the barrier wait.
// MMA issue order: 3 full sweeps over the 8 accumulators per ks.
// 512 thr = 8 independent 2-warp tile groups (32-px tiles, 64-thread
// named barriers).
// in NHWC; out NHWC + fused stats (FINAL: NCHW + relu, no stats).
// =======================================================================
template <bool NORM_IN, bool USE_K, bool FINAL>
__global__ void __launch_bounds__(512, 1)
pac_mma_kernel(const float* __restrict__ in,
               const float* __restrict__ guide,
               const float* __restrict__ w,      // [64][64][3][3] fp32
               const float* __restrict__ bias,
               const float* __restrict__ meanv,
               const float* __restrict__ rstdv,
               float* __restrict__ out,
               float* __restrict__ sums,
               float* __restrict__ sumsqs)
{
    extern __shared__ __align__(16) unsigned char dyn[];
    u32 raw0  = smem_u32(dyn);
    u32 smem0 = (raw0 + 1023) & ~1023u;
    unsigned char* sb = dyn + (smem0 - raw0);

    const int tid  = threadIdx.x;
    const int warp = tid >> 5;
    const int lane = tid & 31;
    const int g    = warp >> 1;        // tile group 0..7
    const int wn   = warp & 1;         // 0/1 : 32-oc half within group
    const int tgl  = wn * 32 + lane;   // thread within group (0..63)
    const int barid = 1 + g;           // named barrier ids 1..8

    // ---- one-time: weights (hi/lo, swizzled rows) + bias ----
    for (int i = tid; i < 36864; i += 512) {
        int oc  = i / 576;
        int r   = i - oc * 576;
        int c   = r / 9;
        int tap = r - c * 9;
        float wv = w[i];
        __nv_bfloat16 hb = __float2bfloat16(wv);
        __nv_bfloat16 lb = __float2bfloat16(wv - __bfloat162float(hb));
        u32 off = swz((u32)(oc * 128 + c * 2));
        *(__nv_bfloat16*)(sb + W_OFF + tap * 16384 +        off) = hb;
        *(__nv_bfloat16*)(sb + W_OFF + tap * 16384 + 8192 + off) = lb;
    }
    if (tid < 64) *(float*)(sb + BIAS_OFF + tid * 4) = bias[tid];
    __syncthreads();

    float2 nm = make_float2(0.f, 0.f), nr = make_float2(1.f, 1.f);
    int cur_b = -1;

    const u32 aBase = A_OFF + g * A_STRIDE;
    const u32 aHi = smem0 + aBase;
    const u32 aLo = aHi + A_LO_REL;
    float* sk = (float*)(sb + K_OFF + g * 1152);
    const int cp   = (lane & 3) * 2;
    const int row4 = lane >> 2;

    // B-operand ldsm row offset (32 oc per warp via two x4 loads)
    const u32 bRowOff = (u32)((wn * 32 + ((lane >> 4) << 3) + (lane & 7)) * 128
                              + ((lane >> 3) & 1) * 16);

    for (int tile = blockIdx.x * 8 + g; tile < 8192; tile += gridDim.x * 8) {
        const int b   = tile >> 11;
        const int rem = tile & 2047;
        const int y   = rem >> 3;
        const int x0  = (rem & 7) << 5;
        int yy[3];
        yy[0] = (y == 0) ? 1 : y - 1;
        yy[1] = y;
        yy[2] = (y == 255) ? 254 : y + 1;

        if (NORM_IN && b != cur_b) {
            nm = *(const float2*)(meanv + b * 64 + 2 * lane);
            nr = *(const float2*)(rstdv + b * 64 + 2 * lane);
            cur_b = b;
        }

        if (USE_K) {
            // Parallel, chain-free k build: 288 independent exps over the
            // full 64-thread group. slot0 = k_8; slots 1-8 = ratios
            // k_{t-1}/k_t computed directly as exp(0.5*(d_t^2-d_{t-1}^2)).
            // sk writes become visible at the first build GBAR below.
            const float* gp = guide + ((size_t)b << 16);
#pragma unroll
            for (int it = 0; it < 5; ++it) {
                int idx = tgl + it * 64;
                if (idx < 288) {
                    int t  = idx >> 5;
                    int px = idx & 31;
                    float gc = gp[y * 256 + x0 + px];
                    if (t == 0) {
                        float gs = gp[yy[2] * 256 + reflx(x0 + px + 1)];
                        float d  = gs - gc;
                        sk[px] = __expf(-0.5f * d * d);        // k_8
                    } else {
                        float gs1 = gp[yy[t / 3] * 256
                                       + reflx(x0 + px + (t % 3) - 1)];
                        float gs0 = gp[yy[(t - 1) / 3] * 256
                                       + reflx(x0 + px + ((t - 1) % 3) - 1)];
                        float d1 = gs1 - gc, d0 = gs0 - gc;
                        float arg = 0.5f * (d1 * d1 - d0 * d0);
                        sk[t * 32 + px] = __expf(fminf(arg, 65.f));
                    }
                }
            }
        }

        float acc[2][4][4];
#pragma unroll
        for (int mi = 0; mi < 2; ++mi)
#pragma unroll
            for (int ni = 0; ni < 4; ++ni)
#pragma unroll
                for (int q = 0; q < 4; ++q) acc[mi][ni][q] = 0.f;

        float k8v[2][2];

        // ---- prologue: prefetch ky=0 rows into registers (17 per warp) ----
        float2 pf[17];
        {
            const float* rowbase =
                in + ((((size_t)b * 256 + yy[0]) * 256) << 6) + 2 * lane;
#pragma unroll
            for (int j = 0; j < 17; ++j) {
                int r = wn + 2 * j;       // rows 0..33
                int xg = x0 - 1 + r;
                xg = xg < 0 ? 1 : (xg > 255 ? 254 : xg);
                pf[j] = *(const float2*)(rowbase + ((size_t)xg << 6));
            }
        }

#pragma unroll
        for (int ky = 0; ky < 3; ++ky) {
            // ---- convert + store prefetched rows (hi/lo, swizzled) ----
#pragma unroll
            for (int j = 0; j < 17; ++j) {
                int r = wn + 2 * j;
                float p0 = pf[j].x, p1 = pf[j].y;
                if (NORM_IN) {
                    p0 = fmaxf((p0 - nm.x) * nr.x, 0.f);
                    p1 = fmaxf((p1 - nm.y) * nr.y, 0.f);
                }
                __nv_bfloat162 h2 = __float22bfloat162_rn(make_float2(p0, p1));
                float l0 = p0 - __bfloat162float(h2.x);
                float l1 = p1 - __bfloat162float(h2.y);
                __nv_bfloat162 lo2 = __float22bfloat162_rn(make_float2(l0, l1));
                u32 off = swz((u32)(r * 128 + lane * 4));
                *(u32*)(sb + aBase + off)            = *(u32*)&h2;
                *(u32*)(sb + aBase + A_LO_REL + off) = *(u32*)&lo2;
            }

            // ---- prefetch next ky BEFORE the barrier (overlaps the wait) ----
            if (ky < 2) {
                const float* rowbase =
                    in + ((((size_t)b * 256 + yy[ky + 1]) * 256) << 6) + 2 * lane;
#pragma unroll
                for (int j = 0; j < 17; ++j) {
                    int r = wn + 2 * j;
                    int xg = x0 - 1 + r;
                    xg = xg < 0 ? 1 : (xg > 255 ? 254 : xg);
                    pf[j] = *(const float2*)(rowbase + ((size_t)xg << 6));
                }
            }
            GBAR(barid);

#pragma unroll
            for (int kx = 0; kx < 3; ++kx) {
                const int t9 = ky * 3 + kx;
                const u32 wHi = smem0 + W_OFF + t9 * 16384;
                const u32 wLo = wHi + 8192;
                // shifted A row offsets (row = px + kx in 34-row tile)
                u32 arow[2];
#pragma unroll
                for (int mi = 0; mi < 2; ++mi)
                    arow[mi] = (u32)(((lane & 15) + mi * 16 + kx) * 128
                                     + (lane >> 4) * 16);

                // rescale acc into 1/k_t space
                if (USE_K && t9 > 0) {
                    float rv[2][2];
#pragma unroll
                    for (int mi = 0; mi < 2; ++mi) {
                        rv[mi][0] = sk[t9 * 32 + mi * 16 + row4];
                        rv[mi][1] = sk[t9 * 32 + mi * 16 + row4 + 8];
                    }
#pragma unroll
                    for (int mi = 0; mi < 2; ++mi)
#pragma unroll
                        for (int ni = 0; ni < 4; ++ni) {
                            acc[mi][ni][0] *= rv[mi][0];
                            acc[mi][ni][1] *= rv[mi][0];
                            acc[mi][ni][2] *= rv[mi][1];
                            acc[mi][ni][3] *= rv[mi][1];
                        }
                }

                // per ks: 8 ldsm upfront, then 3 sweeps of 8 independent mma
#pragma unroll
                for (int ks = 0; ks < 4; ++ks) {
                    u32 afh[2][4], afl[2][4], bh[2][4], bl[2][4];
#pragma unroll
                    for (int mi = 0; mi < 2; ++mi) {
                        ldsm4(afh[mi], aHi + swz(arow[mi] + ks * 32));
                        ldsm4(afl[mi], aLo + swz(arow[mi] + ks * 32));
                    }
#pragma unroll
                    for (int p = 0; p < 2; ++p) {
                        ldsm4(bh[p], wHi + swz(bRowOff + p * 16 * 128 + ks * 32));
                        ldsm4(bl[p], wLo + swz(bRowOff + p * 16 * 128 + ks * 32));
                    }
                    // sweep 1: A-hi x W-hi (8 independent acc)
#pragma unroll
                    for (int mi = 0; mi < 2; ++mi)
#pragma unroll
                        for (int ni = 0; ni < 4; ++ni)
                            mma16816(acc[mi][ni], afh[mi], &bh[ni >> 1][(ni & 1) * 2]);
                    // sweep 2: A-lo x W-hi
#pragma unroll
                    for (int mi = 0; mi < 2; ++mi)
#pragma unroll
                        for (int ni = 0; ni < 4; ++ni)
                            mma16816(acc[mi][ni], afl[mi], &bh[ni >> 1][(ni & 1) * 2]);
                    // sweep 3: A-hi x W-lo
#pragma unroll
                    for (int mi = 0; mi < 2; ++mi)
#pragma unroll
                        for (int ni = 0; ni < 4; ++ni)
                            mma16816(acc[mi][ni], afh[mi], &bl[ni >> 1][(ni & 1) * 2]);
                }
            }
            // load k_8 before the closing barrier (next tile's s_k build
            // happens after this barrier -> no WAR race)
            if (ky == 2 && USE_K) {
#pragma unroll
                for (int mi = 0; mi < 2; ++mi) {
                    k8v[mi][0] = sk[mi * 16 + row4];
                    k8v[mi][1] = sk[mi * 16 + row4 + 8];
                }
            }
            GBAR(barid);   // both group warps done reading A before next build
        }

        // ---- epilogue ----
        if (!FINAL) {
            // direct NHWC float2 stores + fused instance-norm sums
            float2 biasv[4];
#pragma unroll
            for (int ni = 0; ni < 4; ++ni)
                biasv[ni] = *(const float2*)(sb + BIAS_OFF + (wn * 32 + ni * 8 + cp) * 4);
            float sv[8], sq2[8];
#pragma unroll
            for (int q = 0; q < 8; ++q) { sv[q] = 0.f; sq2[q] = 0.f; }
            const size_t rowb = ((((size_t)b * 256 + y) * 256 + x0) << 6);
#pragma unroll
            for (int mi = 0; mi < 2; ++mi) {
                int px = mi * 16 + row4;
                float* p0 = out + rowb + ((size_t)px << 6);
                float* p1 = p0 + (8 << 6);
#pragma unroll
                for (int ni = 0; ni < 4; ++ni) {
                    int oc = wn * 32 + ni * 8 + cp;
                    float v0, v1, v2, v3;
                    if (USE_K) {
                        v0 = fmaf(acc[mi][ni][0], k8v[mi][0], biasv[ni].x);
                        v1 = fmaf(acc[mi][ni][1], k8v[mi][0], biasv[ni].y);
                        v2 = fmaf(acc[mi][ni][2], k8v[mi][1], biasv[ni].x);
                        v3 = fmaf(acc[mi][ni][3], k8v[mi][1], biasv[ni].y);
                    } else {
                        v0 = acc[mi][ni][0] + biasv[ni].x;
                        v1 = acc[mi][ni][1] + biasv[ni].y;
                        v2 = acc[mi][ni][2] + biasv[ni].x;
                        v3 = acc[mi][ni][3] + biasv[ni].y;
                    }
                    *(float2*)(p0 + oc) = make_float2(v0, v1);
                    *(float2*)(p1 + oc) = make_float2(v2, v3);
                    sv[ni * 2 + 0] += v0 + v2;
                    sv[ni * 2 + 1] += v1 + v3;
                    sq2[ni * 2 + 0] = fmaf(v0, v0, fmaf(v2, v2, sq2[ni * 2 + 0]));
                    sq2[ni * 2 + 1] = fmaf(v1, v1, fmaf(v3, v3, sq2[ni * 2 + 1]));
                }
            }
#pragma unroll
            for (int off = 4; off < 32; off <<= 1)
#pragma unroll
                for (int q = 0; q < 8; ++q) {
                    sv[q]  += __shfl_xor_sync(0xffffffffu, sv[q],  off);
                    sq2[q] += __shfl_xor_sync(0xffffffffu, sq2[q], off);
                }
            if (lane < 4) {
#pragma unroll
                for (int ni = 0; ni < 4; ++ni) {
                    int oc = b * 64 + wn * 32 + ni * 8 + lane * 2;
                    atomicAdd(&sums[oc],     sv[ni * 2 + 0]);
                    atomicAdd(&sums[oc + 1], sv[ni * 2 + 1]);
                    atomicAdd(&sumsqs[oc],     sq2[ni * 2 + 0]);
                    atomicAdd(&sumsqs[oc + 1], sq2[ni * 2 + 1]);
                }
            }
        } else {
            // NCHW + bias + relu via group A-region overlay [32][66]
            float* epi = (float*)(sb + aBase);
            {
#pragma unroll
                for (int mi = 0; mi < 2; ++mi)
#pragma unroll
                    for (int ni = 0; ni < 4; ++ni) {
                        int oc = wn * 32 + ni * 8 + cp;
                        int pl = mi * 16 + row4;
                        *(float2*)&epi[pl * 66 + oc] =
                            make_float2(acc[mi][ni][0], acc[mi][ni][1]);
                        *(float2*)&epi[(pl + 8) * 66 + oc] =
                            make_float2(acc[mi][ni][2], acc[mi][ni][3]);
                    }
            }
            GBAR(barid);
            for (int i = tgl; i < 2048; i += 64) {
                int oc = i >> 5, px = i & 31;
                float bv = *(const float*)(sb + BIAS_OFF + oc * 4);
                float v = fmaxf(epi[px * 66 + oc] + bv, 0.f);
                out[((size_t)(b * 64 + oc) << 16) + y * 256 + x0 + px] = v;
            }
            GBAR(barid);   // epi region free before next tile's build
        }
    }
}

// =======================================================================
// Aux kernels (NHWC)
// =======================================================================
__global__ void conv1x1_kernel(const float* __restrict__ x,
                               const float* __restrict__ w0,
                               const float* __restrict__ b0,
                               float* __restrict__ h)   // NHWC out
{
    __shared__ float sw[64], sbv[64];
    int tid = threadIdx.x;
    if (tid < 64) { sw[tid] = w0[tid]; sbv[tid] = b0[tid]; }
    __syncthreads();
    int b = blockIdx.x >> 8, y = blockIdx.x & 255;
    const float* xr = x + ((size_t)b << 16) + y * 256;
    float* ob = h + ((((size_t)b * 256 + y) * 256) << 6);
    int c = tid & 63;
    float wv = sw[c], bv = sbv[c];
    for (int i = 0; i < 64; ++i) {
        int px = i * 4 + (tid >> 6);
        ob[((size_t)px << 6) + c] = fmaf(wv, xr[px], bv);
    }
}

__global__ void finalize_stats_kernel(float* __restrict__ sums,
                                      float* __restrict__ sumsqs,
                                      float* __restrict__ meanv,
                                      float* __restrict__ rstdv)
{
    int bc = threadIdx.x;
    float m   = sums[bc]   * (1.0f / 65536.0f);
    float var = sumsqs[bc] * (1.0f / 65536.0f) - m * m;
    meanv[bc] = m;
    rstdv[bc] = rsqrtf(var + 1e-5f);
    sums[bc] = 0.f;
    sumsqs[bc] = 0.f;
}

__global__ void combine_kernel(float4* __restrict__ h,         // NHWC
                               const float4* __restrict__ t2,
                               const float* __restrict__ meanv,
                               const float* __restrict__ rstdv)
{
    size_t i = (size_t)blockIdx.x * 256 + threadIdx.x;   // 4,194,304 float4
    int c4 = (int)(i & 15);
    int b  = (int)(i >> 20);
    float4 m4 = ((const float4*)meanv)[(b << 4) + c4];
    float4 r4 = ((const float4*)rstdv)[(b << 4) + c4];
    float4 t = t2[i];
    float4 hv = h[i];
    hv.x = fmaxf(hv.x + (t.x - m4.x) * r4.x, 0.f);
    hv.y = fmaxf(hv.y + (t.y - m4.y) * r4.y, 0.f);
    hv.z = fmaxf(hv.z + (t.z - m4.z) * r4.z, 0.f);
    hv.w = fmaxf(hv.w + (t.w - m4.w) * r4.w, 0.f);
    h[i] = hv;
}

// =======================================================================
// launcher
// =======================================================================
extern "C" void kernel_launch(void* const* d_in, const int* in_sizes, int n_in,
                              void* d_out, int out_size)
{
    (void)in_sizes; (void)n_in; (void)out_size;
    const float* x  = (const float*)d_in[0];
    const float* w0 = (const float*)d_in[2];
    const float* b0 = (const float*)d_in[3];
    const float* wf = (const float*)d_in[4];
    const float* bf = (const float*)d_in[5];
    const float* wa[3] = {(const float*)d_in[6],  (const float*)d_in[10], (const float*)d_in[14]};
    const float* ba[3] = {(const float*)d_in[7],  (const float*)d_in[11], (const float*)d_in[15]};
    const float* wb[3] = {(const float*)d_in[8],  (const float*)d_in[12], (const float*)d_in[16]};
    const float* bb[3] = {(const float*)d_in[9],  (const float*)d_in[13], (const float*)d_in[17]};

    float *h, *t1, *t2, *mv, *rv, *sm, *sq;
    cudaGetSymbolAddress((void**)&h,  g_h);
    cudaGetSymbolAddress((void**)&t1, g_t1);
    cudaGetSymbolAddress((void**)&t2, g_t2);
    cudaGetSymbolAddress((void**)&mv, g_mean);
    cudaGetSymbolAddress((void**)&rv, g_rstd);
    cudaGetSymbolAddress((void**)&sm, g_sum);
    cudaGetSymbolAddress((void**)&sq, g_sumsq);

    cudaFuncSetAttribute(pac_mma_kernel<false, true,  false>,
                         cudaFuncAttributeMaxDynamicSharedMemorySize, DSMEM);
    cudaFuncSetAttribute(pac_mma_kernel<true,  true,  false>,
                         cudaFuncAttributeMaxDynamicSharedMemorySize, DSMEM);
    cudaFuncSetAttribute(pac_mma_kernel<false, false, true>,
                         cudaFuncAttributeMaxDynamicSharedMemorySize, DSMEM);

    conv1x1_kernel<<<1024, 256>>>(x, w0, b0, h);

    for (int r = 0; r < 3; ++r) {
        pac_mma_kernel<false, true, false><<<148, 512, DSMEM>>>(
            h, x, wa[r], ba[r], nullptr, nullptr, t1, sm, sq);
        finalize_stats_kernel<<<1, 256>>>(sm, sq, mv, rv);

        pac_mma_kernel<true, true, false><<<148, 512, DSMEM>>>(
            t1, x, wb[r], bb[r], mv, rv, t2, sm, sq);
        finalize_stats_kernel<<<1, 256>>>(sm, sq, mv, rv);

        combine_kernel<<<16384, 256>>>((float4*)h, (const float4*)t2, mv, rv);
    }

    pac_mma_kernel<false, false, true><<<148, 512, DSMEM>>>(
        h, x, wf, bf, nullptr, nullptr, (float*)d_out, sm, sq);
}

// round 17
// speedup vs baseline: 1.0384x; 1.0384x over previous
#include <cuda_runtime.h>
#include <cuda_bf16.h>
#include <cstdint>
#include <cstddef>

typedef unsigned long long u64;
typedef unsigned int u32;

// ---------------- device scratch (no cudaMalloc allowed) ----------------
// NHWC feature buffers [b][y][x][c], 4*256*256*64 floats each
__device__ float g_h [16777216];
__device__ float g_t1[16777216];
__device__ float g_t2[16777216];
// double-buffered instance-norm accumulators (zero-init; kernels re-zero)
__device__ __align__(16) float g_sumA[256];
__device__ __align__(16) float g_sumsqA[256];
__device__ __align__(16) float g_sumB[256];
__device__ __align__(16) float g_sumsqB[256];

// ---------------- helpers ----------------
__device__ __forceinline__ u32 smem_u32(const void* p) {
    u32 a;
    asm("{ .reg .u64 t; cvta.to.shared.u64 t, %1; cvt.u32.u64 %0, t; }"
        : "=r"(a) : "l"(p));
    return a;
}
__device__ __forceinline__ u32 swz(u32 off) { return off ^ ((off >> 3) & 0x70); }
__device__ __forceinline__ int reflx(int i) { return i < 0 ? 1 : (i >= 256 ? 254 : i); }

__device__ __forceinline__ void ldsm4(u32* r, u32 addr) {
    asm volatile("ldmatrix.sync.aligned.m8n8.x4.shared.b16 {%0,%1,%2,%3}, [%4];"
        : "=r"(r[0]), "=r"(r[1]), "=r"(r[2]), "=r"(r[3]) : "r"(addr));
}
__device__ __forceinline__ void mma16816(float* d, const u32* a, const u32* b) {
    asm volatile(
        "mma.sync.aligned.m16n8k16.row.col.f32.bf16.bf16.f32 "
        "{%0,%1,%2,%3}, {%4,%5,%6,%7}, {%8,%9}, {%0,%1,%2,%3};"
        : "+f"(d[0]), "+f"(d[1]), "+f"(d[2]), "+f"(d[3])
        : "r"(a[0]), "r"(a[1]), "r"(a[2]), "r"(a[3]), "r"(b[0]), "r"(b[1]));
}
#define GBAR(id) asm volatile("bar.sync %0, 64;" :: "r"(id) : "memory")

// ---------------- smem layout (relative to 1024-aligned base) ----------------
// [0     : 256   ) bias (64 f32)
// [512   : 9728  ) s_k  float [8 groups][9][32]: slot0 = k_8, slots1-8 = ratios
// [10240 : 157696) W tiles: [tap][hi/lo][64 oc][128B row], swizzled (9*16384)
// [157696: 227328) A tiles: 8 groups x 8704 B (34 rows x 128B, hi then lo)
//                  (FINAL epilogue overlays the group's A region: [32][66] f32)
#define BIAS_OFF  0
#define K_OFF     512
#define W_OFF     10240
#define A_OFF     157696
#define A_STRIDE  8704
#define A_LO_REL  4352
#define DSMEM     (227328 + 1024)

// =======================================================================
// PAC conv via mma.sync, shifted-ldmatrix implicit GEMM (R15-proven core).
// bf16 hi/lo split (3 passes), fp32 accum; guide kernel applied via fp32
// accumulator ratio-rescaling (acc kept in 1/k_t space, k_8 in epilogue).
// A-build LDGs prefetched to registers under the MMA phase.
// MMA issue order: 3 full sweeps over the 8 accumulators per ks.
// 512 thr = 8 independent 2-warp tile groups (32-px tiles, named barriers).
// Instance-norm params computed INLINE from raw sums (no finalize kernel):
//   NORM_IN: nm/nr derived from sums_in/sumsqs_in per batch-change.
//   STATS:   epilogue atomics into sums_out/sumsqs_out.
//   zs/zq:   if non-null, block 0 zeroes them at kernel start (ordered:
//            their writer runs in a later launch).
// in NHWC; out NHWC + fused stats (FINAL: NCHW + relu, no stats).
// =======================================================================
template <bool NORM_IN, bool USE_K, bool FINAL>
__global__ void __launch_bounds__(512, 1)
pac_mma_kernel(const float* __restrict__ in,
               const float* __restrict__ guide,
               const float* __restrict__ w,      // [64][64][3][3] fp32
               const float* __restrict__ bias,
               const float* __restrict__ sums_in,
               const float* __restrict__ sumsqs_in,
               float* __restrict__ out,
               float* __restrict__ sums_out,
               float* __restrict__ sumsqs_out,
               float* __restrict__ zs,
               float* __restrict__ zq)
{
    extern __shared__ __align__(16) unsigned char dyn[];
    u32 raw0  = smem_u32(dyn);
    u32 smem0 = (raw0 + 1023) & ~1023u;
    unsigned char* sb = dyn + (smem0 - raw0);

    const int tid  = threadIdx.x;
    const int warp = tid >> 5;
    const int lane = tid & 31;
    const int g    = warp >> 1;        // tile group 0..7
    const int wn   = warp & 1;         // 0/1 : 32-oc half within group
    const int tgl  = wn * 32 + lane;   // thread within group (0..63)
    const int barid = 1 + g;           // named barrier ids 1..8

    // zero the other stats bank (its writer runs in a later launch)
    if (zs != nullptr && blockIdx.x == 0 && tid < 256) {
        zs[tid] = 0.f;
        zq[tid] = 0.f;
    }

    // ---- one-time: weights (hi/lo, swizzled rows) + bias ----
    for (int i = tid; i < 36864; i += 512) {
        int oc  = i / 576;
        int r   = i - oc * 576;
        int c   = r / 9;
        int tap = r - c * 9;
        float wv = w[i];
        __nv_bfloat16 hb = __float2bfloat16(wv);
        __nv_bfloat16 lb = __float2bfloat16(wv - __bfloat162float(hb));
        u32 off = swz((u32)(oc * 128 + c * 2));
        *(__nv_bfloat16*)(sb + W_OFF + tap * 16384 +        off) = hb;
        *(__nv_bfloat16*)(sb + W_OFF + tap * 16384 + 8192 + off) = lb;
    }
    if (tid < 64) *(float*)(sb + BIAS_OFF + tid * 4) = bias[tid];
    __syncthreads();

    float2 nm = make_float2(0.f, 0.f), nr = make_float2(1.f, 1.f);
    int cur_b = -1;

    const u32 aBase = A_OFF + g * A_STRIDE;
    const u32 aHi = smem0 + aBase;
    const u32 aLo = aHi + A_LO_REL;
    float* sk = (float*)(sb + K_OFF + g * 1152);
    const int cp   = (lane & 3) * 2;
    const int row4 = lane >> 2;

    // B-operand ldsm row offset (32 oc per warp via two x4 loads)
    const u32 bRowOff = (u32)((wn * 32 + ((lane >> 4) << 3) + (lane & 7)) * 128
                              + ((lane >> 3) & 1) * 16);

    for (int tile = blockIdx.x * 8 + g; tile < 8192; tile += gridDim.x * 8) {
        const int b   = tile >> 11;
        const int rem = tile & 2047;
        const int y   = rem >> 3;
        const int x0  = (rem & 7) << 5;
        int yy[3];
        yy[0] = (y == 0) ? 1 : y - 1;
        yy[1] = y;
        yy[2] = (y == 255) ? 254 : y + 1;

        if (NORM_IN && b != cur_b) {
            // inline instance-norm params from raw sums (L1-hot)
            float2 s1 = *(const float2*)(sums_in   + b * 64 + 2 * lane);
            float2 q1 = *(const float2*)(sumsqs_in + b * 64 + 2 * lane);
            nm.x = s1.x * (1.0f / 65536.0f);
            nm.y = s1.y * (1.0f / 65536.0f);
            nr.x = rsqrtf(q1.x * (1.0f / 65536.0f) - nm.x * nm.x + 1e-5f);
            nr.y = rsqrtf(q1.y * (1.0f / 65536.0f) - nm.y * nm.y + 1e-5f);
            cur_b = b;
        }

        if (USE_K && tgl < 32) {
            // per-px serial k chain -> ratios (slots 1-8) + k_8 (slot 0).
            // sk writes become visible at the first build GBAR below.
            const int px = tgl;
            const float* gp = guide + ((size_t)b << 16);
            float gc = gp[y * 256 + x0 + px];
            float kprev = 1.f;
#pragma unroll
            for (int t = 0; t < 9; ++t) {
                float gs = gp[yy[t / 3] * 256 + reflx(x0 + px + (t % 3) - 1)];
                float d  = gs - gc;
                float k  = fmaxf(__expf(-0.5f * d * d), 1e-30f);
                if (t > 0) sk[t * 32 + px] = __fdividef(kprev, k);
                kprev = k;
            }
            sk[px] = kprev;   // k_8
        }

        float acc[2][4][4];
#pragma unroll
        for (int mi = 0; mi < 2; ++mi)
#pragma unroll
            for (int ni = 0; ni < 4; ++ni)
#pragma unroll
                for (int q = 0; q < 4; ++q) acc[mi][ni][q] = 0.f;

        float k8v[2][2];

        // ---- prologue: prefetch ky=0 rows into registers (17 per warp) ----
        float2 pf[17];
        {
            const float* rowbase =
                in + ((((size_t)b * 256 + yy[0]) * 256) << 6) + 2 * lane;
#pragma unroll
            for (int j = 0; j < 17; ++j) {
                int r = wn + 2 * j;       // rows 0..33
                int xg = x0 - 1 + r;
                xg = xg < 0 ? 1 : (xg > 255 ? 254 : xg);
                pf[j] = *(const float2*)(rowbase + ((size_t)xg << 6));
            }
        }

#pragma unroll
        for (int ky = 0; ky < 3; ++ky) {
            // ---- convert + store prefetched rows (hi/lo, swizzled) ----
#pragma unroll
            for (int j = 0; j < 17; ++j) {
                int r = wn + 2 * j;
                float p0 = pf[j].x, p1 = pf[j].y;
                if (NORM_IN) {
                    p0 = fmaxf((p0 - nm.x) * nr.x, 0.f);
                    p1 = fmaxf((p1 - nm.y) * nr.y, 0.f);
                }
                __nv_bfloat162 h2 = __float22bfloat162_rn(make_float2(p0, p1));
                float l0 = p0 - __bfloat162float(h2.x);
                float l1 = p1 - __bfloat162float(h2.y);
                __nv_bfloat162 lo2 = __float22bfloat162_rn(make_float2(l0, l1));
                u32 off = swz((u32)(r * 128 + lane * 4));
                *(u32*)(sb + aBase + off)            = *(u32*)&h2;
                *(u32*)(sb + aBase + A_LO_REL + off) = *(u32*)&lo2;
            }
            GBAR(barid);

            // ---- prefetch next ky under the MMA phase ----
            if (ky < 2) {
                const float* rowbase =
                    in + ((((size_t)b * 256 + yy[ky + 1]) * 256) << 6) + 2 * lane;
#pragma unroll
                for (int j = 0; j < 17; ++j) {
                    int r = wn + 2 * j;
                    int xg = x0 - 1 + r;
                    xg = xg < 0 ? 1 : (xg > 255 ? 254 : xg);
                    pf[j] = *(const float2*)(rowbase + ((size_t)xg << 6));
                }
            }

#pragma unroll
            for (int kx = 0; kx < 3; ++kx) {
                const int t9 = ky * 3 + kx;
                const u32 wHi = smem0 + W_OFF + t9 * 16384;
                const u32 wLo = wHi + 8192;
                // shifted A row offsets (row = px + kx in 34-row tile)
                u32 arow[2];
#pragma unroll
                for (int mi = 0; mi < 2; ++mi)
                    arow[mi] = (u32)(((lane & 15) + mi * 16 + kx) * 128
                                     + (lane >> 4) * 16);

                // rescale acc into 1/k_t space
                if (USE_K && t9 > 0) {
                    float rv[2][2];
#pragma unroll
                    for (int mi = 0; mi < 2; ++mi) {
                        rv[mi][0] = sk[t9 * 32 + mi * 16 + row4];
                        rv[mi][1] = sk[t9 * 32 + mi * 16 + row4 + 8];
                    }
#pragma unroll
                    for (int mi = 0; mi < 2; ++mi)
#pragma unroll
                        for (int ni = 0; ni < 4; ++ni) {
                            acc[mi][ni][0] *= rv[mi][0];
                            acc[mi][ni][1] *= rv[mi][0];
                            acc[mi][ni][2] *= rv[mi][1];
                            acc[mi][ni][3] *= rv[mi][1];
                        }
                }

                // per ks: 8 ldsm upfront, then 3 sweeps of 8 independent mma
#pragma unroll
                for (int ks = 0; ks < 4; ++ks) {
                    u32 afh[2][4], afl[2][4], bh[2][4], bl[2][4];
#pragma unroll
                    for (int mi = 0; mi < 2; ++mi) {
                        ldsm4(afh[mi], aHi + swz(arow[mi] + ks * 32));
                        ldsm4(afl[mi], aLo + swz(arow[mi] + ks * 32));
                    }
#pragma unroll
                    for (int p = 0; p < 2; ++p) {
                        ldsm4(bh[p], wHi + swz(bRowOff + p * 16 * 128 + ks * 32));
                        ldsm4(bl[p], wLo + swz(bRowOff + p * 16 * 128 + ks * 32));
                    }
                    // sweep 1: A-hi x W-hi (8 independent acc)
#pragma unroll
                    for (int mi = 0; mi < 2; ++mi)
#pragma unroll
                        for (int ni = 0; ni < 4; ++ni)
                            mma16816(acc[mi][ni], afh[mi], &bh[ni >> 1][(ni & 1) * 2]);
                    // sweep 2: A-lo x W-hi
#pragma unroll
                    for (int mi = 0; mi < 2; ++mi)
#pragma unroll
                        for (int ni = 0; ni < 4; ++ni)
                            mma16816(acc[mi][ni], afl[mi], &bh[ni >> 1][(ni & 1) * 2]);
                    // sweep 3: A-hi x W-lo
#pragma unroll
                    for (int mi = 0; mi < 2; ++mi)
#pragma unroll
                        for (int ni = 0; ni < 4; ++ni)
                            mma16816(acc[mi][ni], afh[mi], &bl[ni >> 1][(ni & 1) * 2]);
                }
            }
            // load k_8 before the closing barrier (next tile's s_k build
            // happens after this barrier -> no WAR race)
            if (ky == 2 && USE_K) {
#pragma unroll
                for (int mi = 0; mi < 2; ++mi) {
                    k8v[mi][0] = sk[mi * 16 + row4];
                    k8v[mi][1] = sk[mi * 16 + row4 + 8];
                }
            }
            GBAR(barid);   // both group warps done reading A before next build
        }

        // ---- epilogue ----
        if (!FINAL) {
            // direct NHWC float2 stores + fused instance-norm sums
            float2 biasv[4];
#pragma unroll
            for (int ni = 0; ni < 4; ++ni)
                biasv[ni] = *(const float2*)(sb + BIAS_OFF + (wn * 32 + ni * 8 + cp) * 4);
            float sv[8], sq2[8];
#pragma unroll
            for (int q = 0; q < 8; ++q) { sv[q] = 0.f; sq2[q] = 0.f; }
            const size_t rowb = ((((size_t)b * 256 + y) * 256 + x0) << 6);
#pragma unroll
            for (int mi = 0; mi < 2; ++mi) {
                int px = mi * 16 + row4;
                float* p0 = out + rowb + ((size_t)px << 6);
                float* p1 = p0 + (8 << 6);
#pragma unroll
                for (int ni = 0; ni < 4; ++ni) {
                    int oc = wn * 32 + ni * 8 + cp;
                    float v0, v1, v2, v3;
                    if (USE_K) {
                        v0 = fmaf(acc[mi][ni][0], k8v[mi][0], biasv[ni].x);
                        v1 = fmaf(acc[mi][ni][1], k8v[mi][0], biasv[ni].y);
                        v2 = fmaf(acc[mi][ni][2], k8v[mi][1], biasv[ni].x);
                        v3 = fmaf(acc[mi][ni][3], k8v[mi][1], biasv[ni].y);
                    } else {
                        v0 = acc[mi][ni][0] + biasv[ni].x;
                        v1 = acc[mi][ni][1] + biasv[ni].y;
                        v2 = acc[mi][ni][2] + biasv[ni].x;
                        v3 = acc[mi][ni][3] + biasv[ni].y;
                    }
                    *(float2*)(p0 + oc) = make_float2(v0, v1);
                    *(float2*)(p1 + oc) = make_float2(v2, v3);
                    sv[ni * 2 + 0] += v0 + v2;
                    sv[ni * 2 + 1] += v1 + v3;
                    sq2[ni * 2 + 0] = fmaf(v0, v0, fmaf(v2, v2, sq2[ni * 2 + 0]));
                    sq2[ni * 2 + 1] = fmaf(v1, v1, fmaf(v3, v3, sq2[ni * 2 + 1]));
                }
            }
#pragma unroll
            for (int off = 4; off < 32; off <<= 1)
#pragma unroll
                for (int q = 0; q < 8; ++q) {
                    sv[q]  += __shfl_xor_sync(0xffffffffu, sv[q],  off);
                    sq2[q] += __shfl_xor_sync(0xffffffffu, sq2[q], off);
                }
            if (lane < 4) {
#pragma unroll
                for (int ni = 0; ni < 4; ++ni) {
                    int oc = b * 64 + wn * 32 + ni * 8 + lane * 2;
                    atomicAdd(&sums_out[oc],     sv[ni * 2 + 0]);
                    atomicAdd(&sums_out[oc + 1], sv[ni * 2 + 1]);
                    atomicAdd(&sumsqs_out[oc],     sq2[ni * 2 + 0]);
                    atomicAdd(&sumsqs_out[oc + 1], sq2[ni * 2 + 1]);
                }
            }
        } else {
            // NCHW + bias + relu via group A-region overlay [32][66]
            float* epi = (float*)(sb + aBase);
            {
#pragma unroll
                for (int mi = 0; mi < 2; ++mi)
#pragma unroll
                    for (int ni = 0; ni < 4; ++ni) {
                        int oc = wn * 32 + ni * 8 + cp;
                        int pl = mi * 16 + row4;
                        *(float2*)&epi[pl * 66 + oc] =
                            make_float2(acc[mi][ni][0], acc[mi][ni][1]);
                        *(float2*)&epi[(pl + 8) * 66 + oc] =
                            make_float2(acc[mi][ni][2], acc[mi][ni][3]);
                    }
            }
            GBAR(barid);
            for (int i = tgl; i < 2048; i += 64) {
                int oc = i >> 5, px = i & 31;
                float bv = *(const float*)(sb + BIAS_OFF + oc * 4);
                float v = fmaxf(epi[px * 66 + oc] + bv, 0.f);
                out[((size_t)(b * 64 + oc) << 16) + y * 256 + x0 + px] = v;
            }
            GBAR(barid);   // epi region free before next tile's build
        }
    }
}

// =======================================================================
// Aux kernels (NHWC)
// =======================================================================
__global__ void conv1x1_kernel(const float* __restrict__ x,
                               const float* __restrict__ w0,
                               const float* __restrict__ b0,
                               float* __restrict__ h)   // NHWC out
{
    __shared__ float sw[64], sbv[64];
    int tid = threadIdx.x;
    if (tid < 64) { sw[tid] = w0[tid]; sbv[tid] = b0[tid]; }
    __syncthreads();
    int b = blockIdx.x >> 8, y = blockIdx.x & 255;
    const float* xr = x + ((size_t)b << 16) + y * 256;
    float* ob = h + ((((size_t)b * 256 + y) * 256) << 6);
    int c = tid & 63;
    float wv = sw[c], bv = sbv[c];
    for (int i = 0; i < 64; ++i) {
        int px = i * 4 + (tid >> 6);
        ob[((size_t)px << 6) + c] = fmaf(wv, xr[px], bv);
    }
}

// h = relu(h + inorm(t2)); norms computed inline from raw sums (bank B);
// block 0 re-zeroes bank A (its last reader, conv-b, ran in the prior launch).
__global__ void combine_kernel(float4* __restrict__ h,         // NHWC
                               const float4* __restrict__ t2,
                               const float* __restrict__ sumsB,
                               const float* __restrict__ sumsqsB,
                               float* __restrict__ sumsA,
                               float* __restrict__ sumsqsA)
{
    if (blockIdx.x == 0 && threadIdx.x < 256) {
        sumsA[threadIdx.x]   = 0.f;
        sumsqsA[threadIdx.x] = 0.f;
    }
    size_t i = (size_t)blockIdx.x * 256 + threadIdx.x;   // 4,194,304 float4
    int c4 = (int)(i & 15);
    int b  = (int)(i >> 20);
    float4 s4 = ((const float4*)sumsB)[(b << 4) + c4];
    float4 q4 = ((const float4*)sumsqsB)[(b << 4) + c4];
    float4 m4, r4;
    m4.x = s4.x * (1.0f / 65536.0f);
    m4.y = s4.y * (1.0f / 65536.0f);
    m4.z = s4.z * (1.0f / 65536.0f);
    m4.w = s4.w * (1.0f / 65536.0f);
    r4.x = rsqrtf(q4.x * (1.0f / 65536.0f) - m4.x * m4.x + 1e-5f);
    r4.y = rsqrtf(q4.y * (1.0f / 65536.0f) - m4.y * m4.y + 1e-5f);
    r4.z = rsqrtf(q4.z * (1.0f / 65536.0f) - m4.z * m4.z + 1e-5f);
    r4.w = rsqrtf(q4.w * (1.0f / 65536.0f) - m4.w * m4.w + 1e-5f);
    float4 t = t2[i];
    float4 hv = h[i];
    hv.x = fmaxf(hv.x + (t.x - m4.x) * r4.x, 0.f);
    hv.y = fmaxf(hv.y + (t.y - m4.y) * r4.y, 0.f);
    hv.z = fmaxf(hv.z + (t.z - m4.z) * r4.z, 0.f);
    hv.w = fmaxf(hv.w + (t.w - m4.w) * r4.w, 0.f);
    h[i] = hv;
}

// =======================================================================
// launcher
// =======================================================================
extern "C" void kernel_launch(void* const* d_in, const int* in_sizes, int n_in,
                              void* d_out, int out_size)
{
    (void)in_sizes; (void)n_in; (void)out_size;
    const float* x  = (const float*)d_in[0];
    const float* w0 = (const float*)d_in[2];
    const float* b0 = (const float*)d_in[3];
    const float* wf = (const float*)d_in[4];
    const float* bf = (const float*)d_in[5];
    const float* wa[3] = {(const float*)d_in[6],  (const float*)d_in[10], (const float*)d_in[14]};
    const float* ba[3] = {(const float*)d_in[7],  (const float*)d_in[11], (const float*)d_in[15]};
    const float* wb[3] = {(const float*)d_in[8],  (const float*)d_in[12], (const float*)d_in[16]};
    const float* bb[3] = {(const float*)d_in[9],  (const float*)d_in[13], (const float*)d_in[17]};

    float *h, *t1, *t2, *sA, *qA, *sB, *qB;
    cudaGetSymbolAddress((void**)&h,  g_h);
    cudaGetSymbolAddress((void**)&t1, g_t1);
    cudaGetSymbolAddress((void**)&t2, g_t2);
    cudaGetSymbolAddress((void**)&sA, g_sumA);
    cudaGetSymbolAddress((void**)&qA, g_sumsqA);
    cudaGetSymbolAddress((void**)&sB, g_sumB);
    cudaGetSymbolAddress((void**)&qB, g_sumsqB);

    cudaFuncSetAttribute(pac_mma_kernel<false, true,  false>,
                         cudaFuncAttributeMaxDynamicSharedMemorySize, DSMEM);
    cudaFuncSetAttribute(pac_mma_kernel<true,  true,  false>,
                         cudaFuncAttributeMaxDynamicSharedMemorySize, DSMEM);
    cudaFuncSetAttribute(pac_mma_kernel<false, false, true>,
                         cudaFuncAttributeMaxDynamicSharedMemorySize, DSMEM);

    conv1x1_kernel<<<1024, 256>>>(x, w0, b0, h);

    for (int r = 0; r < 3; ++r) {
        // conv-a: stats -> bank A; zeroes bank B (written later by conv-b)
        pac_mma_kernel<false, true, false><<<148, 512, DSMEM>>>(
            h, x, wa[r], ba[r], nullptr, nullptr, t1, sA, qA, sB, qB);

        // conv-b: norm from bank A; stats -> bank B
        pac_mma_kernel<true, true, false><<<148, 512, DSMEM>>>(
            t1, x, wb[r], bb[r], sA, qA, t2, sB, qB, nullptr, nullptr);

        // combine: norm from bank B; zeroes bank A (next conv-a writes it)
        combine_kernel<<<16384, 256>>>((float4*)h, (const float4*)t2,
                                       sB, qB, sA, qA);
    }

    pac_mma_kernel<false, false, true><<<148, 512, DSMEM>>>(
        h, x, wf, bf, nullptr, nullptr, (float*)d_out,
        sA, qA, nullptr, nullptr);
}